// round 5
// baseline (speedup 1.0000x reference)
#include <cuda_runtime.h>
#include <cuda_bf16.h>

// ---------------------------------------------------------------------------
// ISTFTHead: h = x@W + b ; S = min(exp(h_mag),100) * e^{i*phase} ;
// frames = irfft(S, 1024) * hann ; overlap-add hop 256 ; crop PAD=384 ; /env
// Pipeline: [gemm] -> g_h -> [per-frame iFFT+window] -> g_frames -> [OLA gather]
// ---------------------------------------------------------------------------

#define M_TOT   16384      // 8 * 2048 frames
#define K_DIM   512
#define N_DIM   1026
#define NBINS   513
#define NFFT    1024
#define HOP     256
#define PADC    384
#define OUTL    524288     // (2048-1)*256 + 1024 - 2*384 = 525056 - 768
#define NB      8

__device__ float g_h[M_TOT * (long)N_DIM];       // 67.3 MB scratch
__device__ float g_frames[M_TOT * (long)NFFT];   // 67.1 MB scratch (windowed frames)

// ---------------------------------------------------------------------------
// Kernel 1: SGEMM  H[M,N] = A[M,K] * W[K,N] + bias[N]
// BM=128, BN=128, BK=8, 256 threads, 8x8 micro-tile per thread.
// ---------------------------------------------------------------------------
#define BM 128
#define BN 128
#define BK 8

__global__ __launch_bounds__(256) void gemm_kernel(const float* __restrict__ A,
                                                   const float* __restrict__ W,
                                                   const float* __restrict__ bias)
{
    __shared__ float As[BK][BM];
    __shared__ float Bs[BK][BN];

    const int bx = blockIdx.x;        // N tiles (9)
    const int by = blockIdx.y;        // M tiles (128)
    const int tid = threadIdx.x;
    const int tx = tid & 15;          // 0..15  -> 8 cols each
    const int ty = tid >> 4;          // 0..15  -> 8 rows each

    const int aRow = tid >> 1;            // 0..127
    const int aCol = (tid & 1) * 4;       // 0 or 4
    const int bRow = tid >> 5;            // 0..7
    const int bCol = (tid & 31) * 4;      // 0..124

    const float* Ab = A + (long)(by * BM) * K_DIM;

    float acc[8][8];
#pragma unroll
    for (int i = 0; i < 8; i++)
#pragma unroll
        for (int j = 0; j < 8; j++) acc[i][j] = 0.0f;

    for (int k0 = 0; k0 < K_DIM; k0 += BK) {
        // A tile load (always in bounds; K=512 aligned)
        float4 av = *(const float4*)(Ab + (long)aRow * K_DIM + k0 + aCol);
        As[aCol + 0][aRow] = av.x;
        As[aCol + 1][aRow] = av.y;
        As[aCol + 2][aRow] = av.z;
        As[aCol + 3][aRow] = av.w;

        // W tile load: float2 pairs (row stride 4104 B and even col offsets
        // keep 8-byte alignment). Bounds-checked on the last N tile.
        {
            const int krow = k0 + bRow;
            const int gcol = bx * BN + bCol;
            const float* wp = W + (long)krow * N_DIM;
            if (gcol + 3 < N_DIM) {
                float2 w0 = *(const float2*)(wp + gcol);
                float2 w1 = *(const float2*)(wp + gcol + 2);
                Bs[bRow][bCol + 0] = w0.x;
                Bs[bRow][bCol + 1] = w0.y;
                Bs[bRow][bCol + 2] = w1.x;
                Bs[bRow][bCol + 3] = w1.y;
            } else {
                Bs[bRow][bCol + 0] = (gcol + 0 < N_DIM) ? wp[gcol + 0] : 0.0f;
                Bs[bRow][bCol + 1] = (gcol + 1 < N_DIM) ? wp[gcol + 1] : 0.0f;
                Bs[bRow][bCol + 2] = (gcol + 2 < N_DIM) ? wp[gcol + 2] : 0.0f;
                Bs[bRow][bCol + 3] = (gcol + 3 < N_DIM) ? wp[gcol + 3] : 0.0f;
            }
        }
        __syncthreads();

#pragma unroll
        for (int kk = 0; kk < BK; kk++) {
            float ar[8], br[8];
#pragma unroll
            for (int i = 0; i < 8; i++) ar[i] = As[kk][ty * 8 + i];
#pragma unroll
            for (int j = 0; j < 8; j++) br[j] = Bs[kk][tx * 8 + j];
#pragma unroll
            for (int i = 0; i < 8; i++)
#pragma unroll
                for (int j = 0; j < 8; j++)
                    acc[i][j] = fmaf(ar[i], br[j], acc[i][j]);
        }
        __syncthreads();
    }

#pragma unroll
    for (int i = 0; i < 8; i++) {
        const int row = by * BM + ty * 8 + i;
        float* hp = g_h + (long)row * N_DIM;
#pragma unroll
        for (int j = 0; j < 8; j++) {
            const int col = bx * BN + tx * 8 + j;
            if (col < N_DIM) hp[col] = acc[i][j] + bias[col];
        }
    }
}

// ---------------------------------------------------------------------------
// Kernel 2: per-frame spectrum build + inverse FFT (1024, radix-2 DIT) + window
// One CTA (512 threads) per frame. Shared: re/im[1024] + twiddle[512] = 12 KB.
// ---------------------------------------------------------------------------
__global__ __launch_bounds__(512) void istft_frame_kernel()
{
    __shared__ float re[NFFT], im[NFFT];
    __shared__ float twc[NFFT / 2], tws[NFFT / 2];

    const int f   = blockIdx.x;   // 0..16383
    const int tid = threadIdx.x;  // 0..511

    // twiddles: w_j = exp(+i 2*pi*j/1024), j = 0..511 (inverse transform sign)
    {
        float ang = 6.2831853071795864769f * (float)tid * (1.0f / 1024.0f);
        float s, c;
        sincosf(ang, &s, &c);
        twc[tid] = c;
        tws[tid] = s;
    }

    // Build hermitian spectrum in bit-reversed order.
    const float* hrow = g_h + (long)f * N_DIM;
    {
        const int k = tid;                       // bins 0..511; tid 0 also does 512
        float mag = fminf(expf(hrow[k]), 100.0f);
        float p = hrow[NBINS + k];
        float s, c;
        sincosf(p, &s, &c);
        float xr = mag * c, xi = mag * s;
        int r = __brev(k) >> 22;
        re[r] = xr;
        im[r] = xi;
        if (k > 0) {                             // mirror: X[1024-k] = conj(X[k])
            int r2 = __brev(NFFT - k) >> 22;
            re[r2] = xr;
            im[r2] = -xi;
        } else {                                 // Nyquist bin 512
            float mag2 = fminf(expf(hrow[512]), 100.0f);
            float p2 = hrow[NBINS + 512];
            float s2, c2;
            sincosf(p2, &s2, &c2);
            int r3 = __brev(512) >> 22;
            re[r3] = mag2 * c2;
            im[r3] = mag2 * s2;
        }
    }
    __syncthreads();

    // 10 radix-2 stages, one butterfly per thread per stage.
#pragma unroll
    for (int stage = 1; stage <= 10; stage++) {
        const int half = 1 << (stage - 1);
        const int pos  = tid & (half - 1);
        const int idx  = ((tid >> (stage - 1)) << stage) + pos;
        const int ti   = pos << (10 - stage);
        const float c = twc[ti], s = tws[ti];
        const float ur = re[idx],        ui = im[idx];
        const float xr = re[idx + half], xi = im[idx + half];
        const float vr = xr * c - xi * s;
        const float vi = xr * s + xi * c;
        re[idx]        = ur + vr;
        im[idx]        = ui + vi;
        re[idx + half] = ur - vr;
        im[idx + half] = ui - vi;
        __syncthreads();
    }

    // Real part * (1/N) * hann window, to frames scratch.
    float* frow = g_frames + (long)f * NFFT;
#pragma unroll
    for (int n = tid; n < NFFT; n += 512) {
        float w = 0.5f - 0.5f * cosf(6.2831853071795864769f * (float)n * (1.0f / 1024.0f));
        frow[n] = re[n] * (1.0f / 1024.0f) * w;
    }
}

// ---------------------------------------------------------------------------
// Kernel 3: overlap-add gather + envelope division (deterministic).
// Interior samples (covered by exactly 4 frames) use the closed-form hann^2
// COLA constant env = 1.5 (exact trig identity for hop=N/4); edges use the
// explicit loop.
// ---------------------------------------------------------------------------
__global__ __launch_bounds__(256) void ola_kernel(float* __restrict__ out)
{
    const int idx = blockIdx.x * blockDim.x + threadIdx.x;
    if (idx >= NB * OUTL) return;
    const int b = idx / OUTL;
    const int i = idx - b * OUTL;
    const int n = i + PADC;                 // position in un-cropped signal

    const int tmax = min(n >> 8, 2047);
    const int tmin = (n >= NFFT) ? ((n - (NFFT - 1) + (HOP - 1)) >> 8) : 0;

    float sum = 0.0f;
#pragma unroll 4
    for (int t = tmin; t <= tmax; ++t) {
        const int m = n - (t << 8);         // 0..1023
        sum += g_frames[(((long)(b * 2048 + t)) << 10) + m];
    }

    float env;
    if (tmax - tmin == 3) {
        env = 1.5f;                         // 4-term hann^2 COLA sum, exact
    } else {
        env = 0.0f;
        for (int t = tmin; t <= tmax; ++t) {
            const int m = n - (t << 8);
            float w = 0.5f - 0.5f * cosf(6.2831853071795864769f * (float)m * (1.0f / 1024.0f));
            env += w * w;
        }
    }
    out[idx] = sum / env;
}

// ---------------------------------------------------------------------------
extern "C" void kernel_launch(void* const* d_in, const int* in_sizes, int n_in,
                              void* d_out, int out_size)
{
    const float* x    = (const float*)d_in[0];   // [8,2048,512]
    const float* W    = (const float*)d_in[1];   // [512,1026]
    const float* bias = (const float*)d_in[2];   // [1026]
    float* out = (float*)d_out;                  // [8,524288]

    dim3 g1((N_DIM + BN - 1) / BN, M_TOT / BM);  // (9,128)
    gemm_kernel<<<g1, 256>>>(x, W, bias);

    istft_frame_kernel<<<M_TOT, 512>>>();

    const int total = NB * OUTL;
    ola_kernel<<<(total + 255) / 256, 256>>>(out);
}

// round 6
// speedup vs baseline: 1.2293x; 1.2293x over previous
#include <cuda_runtime.h>
#include <cuda_bf16.h>
#include <cstdint>

// ---------------------------------------------------------------------------
// ISTFTHead: h = x@W + b ; S = min(exp(h_mag),100) * e^{i*phase} ;
// frames = irfft(S, 1024) * hann ; overlap-add hop 256 ; crop PAD=384 ; /env
//
// GEMM runs on tensor cores (bf16 mma.sync.m16n8k16) using the split trick:
//   a*b ~= hi_a*hi_b + hi_a*lo_b + lo_a*hi_b   (error ~2^-16, << 1e-3 gate)
// expressed as ONE bf16 GEMM with K' = 3*512 = 1536:
//   A' = [hi_x | hi_x | lo_x]  (row-major, 16384 x 1536)
//   B' = [hi_W ; lo_W ; hi_W]  stored TRANSPOSED n-major (1088 x 1536)
// ---------------------------------------------------------------------------

#define M_TOT   16384      // 8 * 2048 frames
#define K_DIM   512
#define KP      1536       // 3 * K_DIM
#define N_DIM   1026
#define N_PAD   1088       // 17 * 64
#define NBINS   513
#define NFFT    1024
#define HOP     256
#define PADC    384
#define OUTL    524288     // (2048-1)*256 + 1024 - 2*384
#define NB      8

__device__ float         g_h[M_TOT * (long)N_DIM];        // 67.3 MB
__device__ float         g_frames[M_TOT * (long)NFFT];    // 67.1 MB
__device__ __nv_bfloat16 g_Ah[M_TOT * (long)KP];          // 50.3 MB
__device__ __nv_bfloat16 g_Bt[N_PAD * (long)KP];          // 3.3 MB (n-major)
__device__ float         g_twc[512], g_tws[512], g_win[NFFT];

// ---------------------------------------------------------------------------
// Prepass A: split x into (hi, hi, lo) bf16 segments along K'.
// ---------------------------------------------------------------------------
__global__ __launch_bounds__(256) void conv_a_kernel(const float* __restrict__ x)
{
    const long idx = (long)blockIdx.x * 256 + threadIdx.x;   // m*512 + k
    if (idx >= (long)M_TOT * K_DIM) return;
    const long m = idx >> 9;
    const int  k = (int)(idx & 511);
    const float v = x[idx];
    __nv_bfloat16 hi = __float2bfloat16(v);
    __nv_bfloat16 lo = __float2bfloat16(v - __bfloat162float(hi));
    __nv_bfloat16* row = g_Ah + m * KP;
    row[k]        = hi;
    row[k + 512]  = hi;
    row[k + 1024] = lo;
}

// ---------------------------------------------------------------------------
// Prepass B: build transposed, padded B' (n-major): Bt[n][k'] with
// segments [hi_W | lo_W | hi_W] along k'; zeros for n >= 1026.
// ---------------------------------------------------------------------------
__global__ __launch_bounds__(256) void conv_b_kernel(const float* __restrict__ W)
{
    const long idx = (long)blockIdx.x * 256 + threadIdx.x;   // n*1536 + kp
    if (idx >= (long)N_PAD * KP) return;
    const int n  = (int)(idx / KP);
    const int kp = (int)(idx - (long)n * KP);
    __nv_bfloat16 r = __float2bfloat16(0.0f);
    if (n < N_DIM) {
        const int seg = kp >> 9;          // 0,1,2
        const int k   = kp & 511;
        const float v = W[(long)k * N_DIM + n];
        __nv_bfloat16 hi = __float2bfloat16(v);
        if (seg == 1) r = __float2bfloat16(v - __bfloat162float(hi));
        else          r = hi;
    }
    g_Bt[idx] = r;
}

// ---------------------------------------------------------------------------
// Prepass C: twiddle + window tables.
// ---------------------------------------------------------------------------
__global__ void init_tables_kernel()
{
    const int t = threadIdx.x;            // 0..1023
    const float ang = 6.2831853071795864769f * (float)t * (1.0f / 1024.0f);
    if (t < 512) {
        float s, c;
        sincosf(ang, &s, &c);
        g_twc[t] = c;
        g_tws[t] = s;
    }
    g_win[t] = 0.5f - 0.5f * cosf(ang);
}

// ---------------------------------------------------------------------------
// Kernel 1: bf16 tensor-core GEMM  H[M, N] = A'[M, K'] * B'[K', N] + bias
// CTA: 128x64 tile, 256 threads (8 warps as 4x2 of 32x32 warp tiles).
// BK = 32 (two k16 mma steps per smem tile), K' loop = 48 iterations.
// Smem rows padded to 40 halfs -> conflict-free canonical fragment LDS.
// ---------------------------------------------------------------------------
__global__ __launch_bounds__(256) void gemm_mma_kernel(const float* __restrict__ bias)
{
    __shared__ __nv_bfloat16 As[128][40];
    __shared__ __nv_bfloat16 Bs[64][40];

    const int tid  = threadIdx.x;
    const int wid  = tid >> 5;
    const int lane = tid & 31;
    const int gid  = lane >> 2;           // 0..7
    const int tg   = lane & 3;            // 0..3

    const int warp_m = (wid >> 1) * 32;   // 0,32,64,96
    const int warp_n = (wid & 1) * 32;    // 0,32

    const long mbase = (long)blockIdx.y * 128;
    const int  nbase = blockIdx.x * 64;

    // global-load thread mapping
    const int aRow = tid >> 1;            // 0..127
    const int aCb  = (tid & 1) * 16;      // 0 or 16 (halfs)
    const int bRow = tid >> 2;            // 0..63
    const int bCb  = (tid & 3) * 8;       // 0,8,16,24

    const __nv_bfloat16* gA = g_Ah + (mbase + aRow) * (long)KP + aCb;
    const __nv_bfloat16* gB = g_Bt + (long)(nbase + bRow) * KP + bCb;

    float acc[2][4][4];
#pragma unroll
    for (int mi = 0; mi < 2; mi++)
#pragma unroll
        for (int ni = 0; ni < 4; ni++)
#pragma unroll
            for (int e = 0; e < 4; e++) acc[mi][ni][e] = 0.0f;

    // prefetch tile 0
    uint4 ra0 = *(const uint4*)(gA);
    uint4 ra1 = *(const uint4*)(gA + 8);
    uint4 rb  = *(const uint4*)(gB);

    for (int kt = 0; kt < 48; kt++) {
        __syncthreads();
        *(uint4*)&As[aRow][aCb]     = ra0;
        *(uint4*)&As[aRow][aCb + 8] = ra1;
        *(uint4*)&Bs[bRow][bCb]     = rb;
        __syncthreads();

        if (kt < 47) {                    // prefetch next (latency under compute)
            const int off = (kt + 1) * 32;
            ra0 = *(const uint4*)(gA + off);
            ra1 = *(const uint4*)(gA + off + 8);
            rb  = *(const uint4*)(gB + off);
        }

#pragma unroll
        for (int k16 = 0; k16 < 32; k16 += 16) {
            uint32_t af[2][4];
#pragma unroll
            for (int mi = 0; mi < 2; mi++) {
                const __nv_bfloat16* pa = &As[warp_m + mi * 16 + gid][k16 + tg * 2];
                af[mi][0] = *(const uint32_t*)(pa);
                af[mi][1] = *(const uint32_t*)(pa + 8 * 40);
                af[mi][2] = *(const uint32_t*)(pa + 8);
                af[mi][3] = *(const uint32_t*)(pa + 8 * 40 + 8);
            }
            uint32_t bf[4][2];
#pragma unroll
            for (int ni = 0; ni < 4; ni++) {
                const __nv_bfloat16* pb = &Bs[warp_n + ni * 8 + gid][k16 + tg * 2];
                bf[ni][0] = *(const uint32_t*)(pb);
                bf[ni][1] = *(const uint32_t*)(pb + 8);
            }
#pragma unroll
            for (int mi = 0; mi < 2; mi++)
#pragma unroll
                for (int ni = 0; ni < 4; ni++) {
                    asm volatile(
                        "mma.sync.aligned.m16n8k16.row.col.f32.bf16.bf16.f32 "
                        "{%0,%1,%2,%3}, {%4,%5,%6,%7}, {%8,%9}, {%0,%1,%2,%3};\n"
                        : "+f"(acc[mi][ni][0]), "+f"(acc[mi][ni][1]),
                          "+f"(acc[mi][ni][2]), "+f"(acc[mi][ni][3])
                        : "r"(af[mi][0]), "r"(af[mi][1]), "r"(af[mi][2]), "r"(af[mi][3]),
                          "r"(bf[ni][0]), "r"(bf[ni][1]));
                }
        }
    }

    // epilogue: add bias, store to g_h (guard col < 1026)
#pragma unroll
    for (int mi = 0; mi < 2; mi++) {
        const long r0 = mbase + warp_m + mi * 16 + gid;
        const long r1 = r0 + 8;
#pragma unroll
        for (int ni = 0; ni < 4; ni++) {
            const int c0 = nbase + warp_n + ni * 8 + tg * 2;
            if (c0 < N_DIM) {
                const float bb = bias[c0];
                g_h[r0 * N_DIM + c0] = acc[mi][ni][0] + bb;
                g_h[r1 * N_DIM + c0] = acc[mi][ni][2] + bb;
            }
            if (c0 + 1 < N_DIM) {
                const float bb = bias[c0 + 1];
                g_h[r0 * N_DIM + c0 + 1] = acc[mi][ni][1] + bb;
                g_h[r1 * N_DIM + c0 + 1] = acc[mi][ni][3] + bb;
            }
        }
    }
}

// ---------------------------------------------------------------------------
// Kernel 2: per-frame spectrum build + inverse FFT (1024, radix-2) + window.
// Twiddles/window come from precomputed tables (L2-resident).
// ---------------------------------------------------------------------------
__global__ __launch_bounds__(512) void istft_frame_kernel()
{
    __shared__ float re[NFFT], im[NFFT];
    __shared__ float twc[NFFT / 2], tws[NFFT / 2];

    const int f   = blockIdx.x;
    const int tid = threadIdx.x;

    twc[tid] = g_twc[tid];
    tws[tid] = g_tws[tid];

    const float* hrow = g_h + (long)f * N_DIM;
    {
        const int k = tid;
        float mag = fminf(expf(hrow[k]), 100.0f);
        float p = hrow[NBINS + k];
        float s, c;
        sincosf(p, &s, &c);
        float xr = mag * c, xi = mag * s;
        int r = __brev(k) >> 22;
        re[r] = xr;
        im[r] = xi;
        if (k > 0) {
            int r2 = __brev(NFFT - k) >> 22;
            re[r2] = xr;
            im[r2] = -xi;
        } else {
            float mag2 = fminf(expf(hrow[512]), 100.0f);
            float p2 = hrow[NBINS + 512];
            float s2, c2;
            sincosf(p2, &s2, &c2);
            int r3 = __brev(512) >> 22;
            re[r3] = mag2 * c2;
            im[r3] = mag2 * s2;
        }
    }
    __syncthreads();

#pragma unroll
    for (int stage = 1; stage <= 10; stage++) {
        const int half = 1 << (stage - 1);
        const int pos  = tid & (half - 1);
        const int idx  = ((tid >> (stage - 1)) << stage) + pos;
        const int ti   = pos << (10 - stage);
        const float c = twc[ti], s = tws[ti];
        const float ur = re[idx],        ui = im[idx];
        const float xr = re[idx + half], xi = im[idx + half];
        const float vr = xr * c - xi * s;
        const float vi = xr * s + xi * c;
        re[idx]        = ur + vr;
        im[idx]        = ui + vi;
        re[idx + half] = ur - vr;
        im[idx + half] = ui - vi;
        __syncthreads();
    }

    float* frow = g_frames + (long)f * NFFT;
#pragma unroll
    for (int n = tid; n < NFFT; n += 512) {
        frow[n] = re[n] * (1.0f / 1024.0f) * g_win[n];
    }
}

// ---------------------------------------------------------------------------
// Kernel 3: overlap-add gather + envelope division.
// Interior samples use the exact hann^2 COLA constant 1.5.
// ---------------------------------------------------------------------------
__global__ __launch_bounds__(256) void ola_kernel(float* __restrict__ out)
{
    const int idx = blockIdx.x * blockDim.x + threadIdx.x;
    if (idx >= NB * OUTL) return;
    const int b = idx / OUTL;
    const int i = idx - b * OUTL;
    const int n = i + PADC;

    const int tmax = min(n >> 8, 2047);
    const int tmin = (n >= NFFT) ? ((n - (NFFT - 1) + (HOP - 1)) >> 8) : 0;

    float sum = 0.0f;
#pragma unroll 4
    for (int t = tmin; t <= tmax; ++t) {
        const int m = n - (t << 8);
        sum += g_frames[(((long)(b * 2048 + t)) << 10) + m];
    }

    float env;
    if (tmax - tmin == 3) {
        env = 1.5f;
    } else {
        env = 0.0f;
        for (int t = tmin; t <= tmax; ++t) {
            const int m = n - (t << 8);
            float w = 0.5f - 0.5f * cosf(6.2831853071795864769f * (float)m * (1.0f / 1024.0f));
            env += w * w;
        }
    }
    out[idx] = sum / env;
}

// ---------------------------------------------------------------------------
extern "C" void kernel_launch(void* const* d_in, const int* in_sizes, int n_in,
                              void* d_out, int out_size)
{
    const float* x    = (const float*)d_in[0];   // [8,2048,512]
    const float* W    = (const float*)d_in[1];   // [512,1026]
    const float* bias = (const float*)d_in[2];   // [1026]
    float* out = (float*)d_out;                  // [8,524288]

    {   // prepasses
        const long na = (long)M_TOT * K_DIM;
        conv_a_kernel<<<(unsigned)((na + 255) / 256), 256>>>(x);
        const long nb = (long)N_PAD * KP;
        conv_b_kernel<<<(unsigned)((nb + 255) / 256), 256>>>(W);
        init_tables_kernel<<<1, 1024>>>();
    }

    dim3 gg(N_PAD / 64, M_TOT / 128);            // (17, 128)
    gemm_mma_kernel<<<gg, 256>>>(bias);

    istft_frame_kernel<<<M_TOT, 512>>>();

    const int total = NB * OUTL;
    ola_kernel<<<(total + 255) / 256, 256>>>(out);
}

// round 7
// speedup vs baseline: 1.5955x; 1.2979x over previous
#include <cuda_runtime.h>
#include <cuda_bf16.h>
#include <cstdint>

// ---------------------------------------------------------------------------
// ISTFTHead: h = x@W + b ; S = min(exp(h_mag),100) * e^{i*phase} ;
// frames = irfft(S, 1024) * hann ; overlap-add hop 256 ; crop PAD=384 ; /env
//
// GEMM on tensor cores (bf16 mma.sync m16n8k16, ldmatrix fragments) with the
// fp32 split trick as a single bf16 GEMM, K' = 3*512:
//   A' = [hi_x | hi_x | lo_x]   B' = [hi_W ; lo_W ; hi_W] (transposed n-major)
// ---------------------------------------------------------------------------

#define M_TOT   16384
#define K_DIM   512
#define KP      1536
#define N_DIM   1026
#define N_PAD   1152       // 9 * 128
#define NBINS   513
#define NFFT    1024
#define HOP     256
#define PADC    384
#define OUTL    524288
#define NB      8

__device__ float         g_h[M_TOT * (long)N_DIM];
__device__ float         g_frames[M_TOT * (long)NFFT];
__device__ __nv_bfloat16 g_Ah[M_TOT * (long)KP];
__device__ __nv_bfloat16 g_Bt[N_PAD * (long)KP];
__device__ float         g_twc[512], g_tws[512], g_win[NFFT];

static __device__ __forceinline__ uint32_t s2u(const void* p)
{
    return (uint32_t)__cvta_generic_to_shared(p);
}

// ---------------------------------------------------------------------------
// Prepass A: split x into (hi, hi, lo) bf16 segments along K'.
// ---------------------------------------------------------------------------
__global__ __launch_bounds__(256) void conv_a_kernel(const float* __restrict__ x)
{
    const long idx = (long)blockIdx.x * 256 + threadIdx.x;
    if (idx >= (long)M_TOT * K_DIM) return;
    const long m = idx >> 9;
    const int  k = (int)(idx & 511);
    const float v = x[idx];
    __nv_bfloat16 hi = __float2bfloat16(v);
    __nv_bfloat16 lo = __float2bfloat16(v - __bfloat162float(hi));
    __nv_bfloat16* row = g_Ah + m * KP;
    row[k]        = hi;
    row[k + 512]  = hi;
    row[k + 1024] = lo;
}

// ---------------------------------------------------------------------------
// Prepass B: transposed padded B' (n-major): segments [hi_W | lo_W | hi_W].
// ---------------------------------------------------------------------------
__global__ __launch_bounds__(256) void conv_b_kernel(const float* __restrict__ W)
{
    const long idx = (long)blockIdx.x * 256 + threadIdx.x;
    if (idx >= (long)N_PAD * KP) return;
    const int n  = (int)(idx / KP);
    const int kp = (int)(idx - (long)n * KP);
    __nv_bfloat16 r = __float2bfloat16(0.0f);
    if (n < N_DIM) {
        const int seg = kp >> 9;
        const int k   = kp & 511;
        const float v = W[(long)k * N_DIM + n];
        __nv_bfloat16 hi = __float2bfloat16(v);
        if (seg == 1) r = __float2bfloat16(v - __bfloat162float(hi));
        else          r = hi;
    }
    g_Bt[idx] = r;
}

// ---------------------------------------------------------------------------
// Prepass C: twiddle + window tables (precise sincosf here).
// ---------------------------------------------------------------------------
__global__ void init_tables_kernel()
{
    const int t = threadIdx.x;
    const float ang = 6.2831853071795864769f * (float)t * (1.0f / 1024.0f);
    if (t < 512) {
        float s, c;
        sincosf(ang, &s, &c);
        g_twc[t] = c;
        g_tws[t] = s;
    }
    g_win[t] = 0.5f - 0.5f * cosf(ang);
}

// ---------------------------------------------------------------------------
// Kernel 1: bf16 mma GEMM. CTA 128x128, 8 warps (4m x 2n) of 32x64 tiles.
// BK = 32, double-buffered smem, ldmatrix.x4 fragment loads.
// Smem rows padded to 40 halfs (80 B) -> conflict-free LDSM.
// ---------------------------------------------------------------------------
__global__ __launch_bounds__(256, 2) void gemm_mma_kernel(const float* __restrict__ bias)
{
    __shared__ __nv_bfloat16 As[2][128][40];
    __shared__ __nv_bfloat16 Bs[2][128][40];

    const int tid  = threadIdx.x;
    const int wid  = tid >> 5;
    const int lane = tid & 31;
    const int gid  = lane >> 2;
    const int tg   = lane & 3;

    const int warp_m = (wid >> 1) * 32;   // 0,32,64,96
    const int warp_n = (wid & 1) * 64;    // 0,64

    const long mbase = (long)blockIdx.y * 128;
    const int  nbase = blockIdx.x * 128;

    const int row = tid >> 1;             // 0..127
    const int cb  = (tid & 1) * 16;       // 0 or 16 halfs

    const __nv_bfloat16* gA = g_Ah + (mbase + row) * (long)KP + cb;
    const __nv_bfloat16* gB = g_Bt + (long)(nbase + row) * KP + cb;

    // lane addresses for ldmatrix (bytes within CTA smem)
    const int aR = (lane & 15);
    const int aC = (lane >> 4) << 3;
    const int bR = (lane & 7) + ((lane >> 4) << 3);
    const int bC = ((lane >> 3) & 1) << 3;

    float acc[2][4][2][4];                // [mi][np][sub][e]
#pragma unroll
    for (int mi = 0; mi < 2; mi++)
#pragma unroll
        for (int np = 0; np < 4; np++)
#pragma unroll
            for (int s = 0; s < 2; s++)
#pragma unroll
                for (int e = 0; e < 4; e++) acc[mi][np][s][e] = 0.0f;

    // tile 0
    {
        uint4 ra0 = *(const uint4*)(gA);
        uint4 ra1 = *(const uint4*)(gA + 8);
        uint4 rb0 = *(const uint4*)(gB);
        uint4 rb1 = *(const uint4*)(gB + 8);
        *(uint4*)&As[0][row][cb]     = ra0;
        *(uint4*)&As[0][row][cb + 8] = ra1;
        *(uint4*)&Bs[0][row][cb]     = rb0;
        *(uint4*)&Bs[0][row][cb + 8] = rb1;
    }
    __syncthreads();

    uint4 ra0, ra1, rb0, rb1;
    for (int kt = 0; kt < 48; kt++) {
        const int cur = kt & 1, nxt = cur ^ 1;
        if (kt < 47) {
            const int off = (kt + 1) * 32;
            ra0 = *(const uint4*)(gA + off);
            ra1 = *(const uint4*)(gA + off + 8);
            rb0 = *(const uint4*)(gB + off);
            rb1 = *(const uint4*)(gB + off + 8);
        }

#pragma unroll
        for (int k16 = 0; k16 < 32; k16 += 16) {
            uint32_t af[2][4];
#pragma unroll
            for (int mi = 0; mi < 2; mi++) {
                uint32_t addr = s2u(&As[cur][warp_m + mi * 16 + aR][k16 + aC]);
                asm volatile(
                    "ldmatrix.sync.aligned.m8n8.x4.shared.b16 {%0,%1,%2,%3}, [%4];"
                    : "=r"(af[mi][0]), "=r"(af[mi][1]), "=r"(af[mi][2]), "=r"(af[mi][3])
                    : "r"(addr));
            }
            uint32_t bf[4][4];
#pragma unroll
            for (int np = 0; np < 4; np++) {
                uint32_t addr = s2u(&Bs[cur][warp_n + np * 16 + bR][k16 + bC]);
                asm volatile(
                    "ldmatrix.sync.aligned.m8n8.x4.shared.b16 {%0,%1,%2,%3}, [%4];"
                    : "=r"(bf[np][0]), "=r"(bf[np][1]), "=r"(bf[np][2]), "=r"(bf[np][3])
                    : "r"(addr));
            }
#pragma unroll
            for (int mi = 0; mi < 2; mi++)
#pragma unroll
                for (int np = 0; np < 4; np++) {
                    asm volatile(
                        "mma.sync.aligned.m16n8k16.row.col.f32.bf16.bf16.f32 "
                        "{%0,%1,%2,%3}, {%4,%5,%6,%7}, {%8,%9}, {%0,%1,%2,%3};\n"
                        : "+f"(acc[mi][np][0][0]), "+f"(acc[mi][np][0][1]),
                          "+f"(acc[mi][np][0][2]), "+f"(acc[mi][np][0][3])
                        : "r"(af[mi][0]), "r"(af[mi][1]), "r"(af[mi][2]), "r"(af[mi][3]),
                          "r"(bf[np][0]), "r"(bf[np][1]));
                    asm volatile(
                        "mma.sync.aligned.m16n8k16.row.col.f32.bf16.bf16.f32 "
                        "{%0,%1,%2,%3}, {%4,%5,%6,%7}, {%8,%9}, {%0,%1,%2,%3};\n"
                        : "+f"(acc[mi][np][1][0]), "+f"(acc[mi][np][1][1]),
                          "+f"(acc[mi][np][1][2]), "+f"(acc[mi][np][1][3])
                        : "r"(af[mi][0]), "r"(af[mi][1]), "r"(af[mi][2]), "r"(af[mi][3]),
                          "r"(bf[np][2]), "r"(bf[np][3]));
                }
        }

        if (kt < 47) {
            *(uint4*)&As[nxt][row][cb]     = ra0;
            *(uint4*)&As[nxt][row][cb + 8] = ra1;
            *(uint4*)&Bs[nxt][row][cb]     = rb0;
            *(uint4*)&Bs[nxt][row][cb + 8] = rb1;
        }
        __syncthreads();
    }

    // epilogue: bias + store (guard col < 1026)
#pragma unroll
    for (int mi = 0; mi < 2; mi++) {
        const long r0 = mbase + warp_m + mi * 16 + gid;
        const long r1 = r0 + 8;
#pragma unroll
        for (int np = 0; np < 4; np++)
#pragma unroll
            for (int s = 0; s < 2; s++) {
                const int c0 = nbase + warp_n + np * 16 + s * 8 + tg * 2;
                if (c0 < N_DIM) {
                    const float bb = bias[c0];
                    g_h[r0 * N_DIM + c0] = acc[mi][np][s][0] + bb;
                    g_h[r1 * N_DIM + c0] = acc[mi][np][s][2] + bb;
                }
                if (c0 + 1 < N_DIM) {
                    const float bb = bias[c0 + 1];
                    g_h[r0 * N_DIM + c0 + 1] = acc[mi][np][s][1] + bb;
                    g_h[r1 * N_DIM + c0 + 1] = acc[mi][np][s][3] + bb;
                }
            }
    }
}

// ---------------------------------------------------------------------------
// Kernel 2: spectrum build + inverse FFT 1024 (5 radix-4 stages) + window.
// 256 threads/CTA; bit-reversed input layout; stage pair (2p+1, 2p+2) of the
// radix-2 DIT merged into one radix-4 butterfly in registers.
// ---------------------------------------------------------------------------
__global__ __launch_bounds__(256) void istft_frame_kernel()
{
    __shared__ float re[NFFT], im[NFFT];
    __shared__ float twc[512], tws[512];

    const int f   = blockIdx.x;
    const int tid = threadIdx.x;   // 0..255

    twc[tid]       = g_twc[tid];
    tws[tid]       = g_tws[tid];
    twc[tid + 256] = g_twc[tid + 256];
    tws[tid + 256] = g_tws[tid + 256];

    const float* hrow = g_h + (long)f * N_DIM;
#pragma unroll
    for (int k = tid; k < 512; k += 256) {
        float mag = fminf(__expf(hrow[k]), 100.0f);
        float p = hrow[NBINS + k];
        float s, c;
        __sincosf(p, &s, &c);
        float xr = mag * c, xi = mag * s;
        int r = __brev(k) >> 22;
        re[r] = xr;
        im[r] = xi;
        if (k > 0) {
            int r2 = __brev(NFFT - k) >> 22;
            re[r2] = xr;
            im[r2] = -xi;
        } else {
            float mag2 = fminf(__expf(hrow[512]), 100.0f);
            float p2 = hrow[NBINS + 512];
            float s2, c2;
            __sincosf(p2, &s2, &c2);
            int r3 = __brev(512) >> 22;
            re[r3] = mag2 * c2;
            im[r3] = mag2 * s2;
        }
    }
    __syncthreads();

#pragma unroll
    for (int p = 0; p < 5; p++) {
        const int q    = 1 << (2 * p);
        const int pos  = tid & (q - 1);
        const int base = ((tid >> (2 * p)) << (2 * p + 2)) + pos;
        const float w1c = twc[pos << (9 - 2 * p)], w1s = tws[pos << (9 - 2 * p)];
        const float w2c = twc[pos << (8 - 2 * p)], w2s = tws[pos << (8 - 2 * p)];

        const float e0r = re[base],         e0i = im[base];
        const float e1r = re[base + q],     e1i = im[base + q];
        const float e2r = re[base + 2 * q], e2i = im[base + 2 * q];
        const float e3r = re[base + 3 * q], e3i = im[base + 3 * q];

        const float t1r = e1r * w1c - e1i * w1s, t1i = e1r * w1s + e1i * w1c;
        const float t3r = e3r * w1c - e3i * w1s, t3i = e3r * w1s + e3i * w1c;
        const float u0r = e0r + t1r, u0i = e0i + t1i;
        const float v0r = e0r - t1r, v0i = e0i - t1i;
        const float u1r = e2r + t3r, u1i = e2i + t3i;
        const float v1r = e2r - t3r, v1i = e2i - t3i;

        const float a1r = u1r * w2c - u1i * w2s, a1i = u1r * w2s + u1i * w2c;
        const float b1r = v1r * w2c - v1i * w2s, b1i = v1r * w2s + v1i * w2c;

        re[base]         = u0r + a1r;  im[base]         = u0i + a1i;
        re[base + 2 * q] = u0r - a1r;  im[base + 2 * q] = u0i - a1i;
        re[base + q]     = v0r - b1i;  im[base + q]     = v0i + b1r;
        re[base + 3 * q] = v0r + b1i;  im[base + 3 * q] = v0i - b1r;
        __syncthreads();
    }

    float* frow = g_frames + (long)f * NFFT;
#pragma unroll
    for (int n = tid; n < NFFT; n += 256) {
        frow[n] = re[n] * (1.0f / 1024.0f) * g_win[n];
    }
}

// ---------------------------------------------------------------------------
// Kernel 3: overlap-add + envelope (interior env == 1.5 exactly).
// ---------------------------------------------------------------------------
__global__ __launch_bounds__(256) void ola_kernel(float* __restrict__ out)
{
    const int idx = blockIdx.x * blockDim.x + threadIdx.x;
    if (idx >= NB * OUTL) return;
    const int b = idx / OUTL;
    const int i = idx - b * OUTL;
    const int n = i + PADC;

    const int tmax = min(n >> 8, 2047);
    const int tmin = (n >= NFFT) ? ((n - (NFFT - 1) + (HOP - 1)) >> 8) : 0;

    float sum = 0.0f;
#pragma unroll 4
    for (int t = tmin; t <= tmax; ++t) {
        const int m = n - (t << 8);
        sum += g_frames[(((long)(b * 2048 + t)) << 10) + m];
    }

    float env;
    if (tmax - tmin == 3) {
        env = 1.5f;
    } else {
        env = 0.0f;
        for (int t = tmin; t <= tmax; ++t) {
            const int m = n - (t << 8);
            float w = 0.5f - 0.5f * cosf(6.2831853071795864769f * (float)m * (1.0f / 1024.0f));
            env += w * w;
        }
    }
    out[idx] = sum / env;
}

// ---------------------------------------------------------------------------
extern "C" void kernel_launch(void* const* d_in, const int* in_sizes, int n_in,
                              void* d_out, int out_size)
{
    const float* x    = (const float*)d_in[0];
    const float* W    = (const float*)d_in[1];
    const float* bias = (const float*)d_in[2];
    float* out = (float*)d_out;

    {
        const long na = (long)M_TOT * K_DIM;
        conv_a_kernel<<<(unsigned)((na + 255) / 256), 256>>>(x);
        const long nb = (long)N_PAD * KP;
        conv_b_kernel<<<(unsigned)((nb + 255) / 256), 256>>>(W);
        init_tables_kernel<<<1, 1024>>>();
    }

    dim3 gg(N_PAD / 128, M_TOT / 128);           // (9, 128)
    gemm_mma_kernel<<<gg, 256>>>(bias);

    istft_frame_kernel<<<M_TOT, 256>>>();

    const int total = NB * OUTL;
    ola_kernel<<<(total + 255) / 256, 256>>>(out);
}

// round 14
// speedup vs baseline: 2.2189x; 1.3907x over previous
#include <cuda_runtime.h>
#include <cuda_bf16.h>
#include <cstdint>

// ---------------------------------------------------------------------------
// ISTFTHead: h = x@W + b (bf16 mma.sync split-fp32 GEMM, K'=3*512);
// irfft(1024) via half-size 512-pt complex radix-8 iFFT; hann window;
// overlap-add hop 256; crop PAD=384; COLA envelope division.
// NOTE: harness compiles via compute_103 (no 'a') => tcgen05 unavailable;
// mma.sync/ldmatrix are the tensor path on this target.
// ---------------------------------------------------------------------------

#define M_TOT   16384
#define K_DIM   512
#define KP      1536
#define N_DIM   1026
#define N_PAD   1152       // 9 * 128
#define NBINS   513
#define NFFT    1024
#define HOP     256
#define PADC    384
#define OUTL    524288
#define NB      8

__device__ float         g_h[M_TOT * (long)N_DIM];
__device__ float         g_frames[M_TOT * (long)NFFT];
__device__ __nv_bfloat16 g_Ah[M_TOT * (long)KP];
__device__ __nv_bfloat16 g_Bt[N_PAD * (long)KP];
__device__ float         g_twc[512], g_tws[512];     // e^{+2pi i k/1024}
__device__ float         g_t5c[512], g_t5s[512];     // e^{+2pi i m/512}
__device__ float         g_win[NFFT];

static __device__ __forceinline__ uint32_t s2u(const void* p)
{
    return (uint32_t)__cvta_generic_to_shared(p);
}

// ---------------------------------------------------------------------------
// Prepass A: split x into (hi, hi, lo) bf16 segments along K'.
// ---------------------------------------------------------------------------
__global__ __launch_bounds__(256) void conv_a_kernel(const float* __restrict__ x)
{
    const long idx = (long)blockIdx.x * 256 + threadIdx.x;
    if (idx >= (long)M_TOT * K_DIM) return;
    const long m = idx >> 9;
    const int  k = (int)(idx & 511);
    const float v = x[idx];
    __nv_bfloat16 hi = __float2bfloat16(v);
    __nv_bfloat16 lo = __float2bfloat16(v - __bfloat162float(hi));
    __nv_bfloat16* row = g_Ah + m * KP;
    row[k]        = hi;
    row[k + 512]  = hi;
    row[k + 1024] = lo;
}

// ---------------------------------------------------------------------------
// Prepass B: transposed padded B' (n-major): segments [hi_W | lo_W | hi_W].
// ---------------------------------------------------------------------------
__global__ __launch_bounds__(256) void conv_b_kernel(const float* __restrict__ W)
{
    const long idx = (long)blockIdx.x * 256 + threadIdx.x;
    if (idx >= (long)N_PAD * KP) return;
    const int n  = (int)(idx / KP);
    const int kp = (int)(idx - (long)n * KP);
    __nv_bfloat16 r = __float2bfloat16(0.0f);
    if (n < N_DIM) {
        const int seg = kp >> 9;
        const int k   = kp & 511;
        const float v = W[(long)k * N_DIM + n];
        __nv_bfloat16 hi = __float2bfloat16(v);
        if (seg == 1) r = __float2bfloat16(v - __bfloat162float(hi));
        else          r = hi;
    }
    g_Bt[idx] = r;
}

// ---------------------------------------------------------------------------
// Prepass C: twiddle + window tables (precise sincosf).
// ---------------------------------------------------------------------------
__global__ void init_tables_kernel()
{
    const int t = threadIdx.x;               // 0..1023
    const float ang = 6.2831853071795864769f * (float)t * (1.0f / 1024.0f);
    if (t < 512) {
        float s, c;
        sincosf(ang, &s, &c);
        g_twc[t] = c;
        g_tws[t] = s;
        float s2, c2;
        sincosf(6.2831853071795864769f * (float)t * (1.0f / 512.0f), &s2, &c2);
        g_t5c[t] = c2;
        g_t5s[t] = s2;
    }
    g_win[t] = 0.5f - 0.5f * cosf(ang);
}

// ---------------------------------------------------------------------------
// Kernel 1: bf16 mma GEMM (R7, measured 264us). CTA 128x128, 8 warps of
// 32x64, BK=32, double-buffered smem, ldmatrix.x4, rows padded to 40 halfs.
// ---------------------------------------------------------------------------
__global__ __launch_bounds__(256, 2) void gemm_mma_kernel(const float* __restrict__ bias)
{
    __shared__ __nv_bfloat16 As[2][128][40];
    __shared__ __nv_bfloat16 Bs[2][128][40];

    const int tid  = threadIdx.x;
    const int wid  = tid >> 5;
    const int lane = tid & 31;
    const int gid  = lane >> 2;
    const int tg   = lane & 3;

    const int warp_m = (wid >> 1) * 32;
    const int warp_n = (wid & 1) * 64;

    const long mbase = (long)blockIdx.y * 128;
    const int  nbase = blockIdx.x * 128;

    const int row = tid >> 1;
    const int cb  = (tid & 1) * 16;

    const __nv_bfloat16* gA = g_Ah + (mbase + row) * (long)KP + cb;
    const __nv_bfloat16* gB = g_Bt + (long)(nbase + row) * KP + cb;

    const int aR = (lane & 15);
    const int aC = (lane >> 4) << 3;
    const int bR = (lane & 7) + ((lane >> 4) << 3);
    const int bC = ((lane >> 3) & 1) << 3;

    float acc[2][4][2][4];
#pragma unroll
    for (int mi = 0; mi < 2; mi++)
#pragma unroll
        for (int np = 0; np < 4; np++)
#pragma unroll
            for (int s = 0; s < 2; s++)
#pragma unroll
                for (int e = 0; e < 4; e++) acc[mi][np][s][e] = 0.0f;

    {
        uint4 ra0 = *(const uint4*)(gA);
        uint4 ra1 = *(const uint4*)(gA + 8);
        uint4 rb0 = *(const uint4*)(gB);
        uint4 rb1 = *(const uint4*)(gB + 8);
        *(uint4*)&As[0][row][cb]     = ra0;
        *(uint4*)&As[0][row][cb + 8] = ra1;
        *(uint4*)&Bs[0][row][cb]     = rb0;
        *(uint4*)&Bs[0][row][cb + 8] = rb1;
    }
    __syncthreads();

    uint4 ra0, ra1, rb0, rb1;
    for (int kt = 0; kt < 48; kt++) {
        const int cur = kt & 1, nxt = cur ^ 1;
        if (kt < 47) {
            const int off = (kt + 1) * 32;
            ra0 = *(const uint4*)(gA + off);
            ra1 = *(const uint4*)(gA + off + 8);
            rb0 = *(const uint4*)(gB + off);
            rb1 = *(const uint4*)(gB + off + 8);
        }

#pragma unroll
        for (int k16 = 0; k16 < 32; k16 += 16) {
            uint32_t af[2][4];
#pragma unroll
            for (int mi = 0; mi < 2; mi++) {
                uint32_t addr = s2u(&As[cur][warp_m + mi * 16 + aR][k16 + aC]);
                asm volatile(
                    "ldmatrix.sync.aligned.m8n8.x4.shared.b16 {%0,%1,%2,%3}, [%4];"
                    : "=r"(af[mi][0]), "=r"(af[mi][1]), "=r"(af[mi][2]), "=r"(af[mi][3])
                    : "r"(addr));
            }
            uint32_t bf[4][4];
#pragma unroll
            for (int np = 0; np < 4; np++) {
                uint32_t addr = s2u(&Bs[cur][warp_n + np * 16 + bR][k16 + bC]);
                asm volatile(
                    "ldmatrix.sync.aligned.m8n8.x4.shared.b16 {%0,%1,%2,%3}, [%4];"
                    : "=r"(bf[np][0]), "=r"(bf[np][1]), "=r"(bf[np][2]), "=r"(bf[np][3])
                    : "r"(addr));
            }
#pragma unroll
            for (int mi = 0; mi < 2; mi++)
#pragma unroll
                for (int np = 0; np < 4; np++) {
                    asm volatile(
                        "mma.sync.aligned.m16n8k16.row.col.f32.bf16.bf16.f32 "
                        "{%0,%1,%2,%3}, {%4,%5,%6,%7}, {%8,%9}, {%0,%1,%2,%3};\n"
                        : "+f"(acc[mi][np][0][0]), "+f"(acc[mi][np][0][1]),
                          "+f"(acc[mi][np][0][2]), "+f"(acc[mi][np][0][3])
                        : "r"(af[mi][0]), "r"(af[mi][1]), "r"(af[mi][2]), "r"(af[mi][3]),
                          "r"(bf[np][0]), "r"(bf[np][1]));
                    asm volatile(
                        "mma.sync.aligned.m16n8k16.row.col.f32.bf16.bf16.f32 "
                        "{%0,%1,%2,%3}, {%4,%5,%6,%7}, {%8,%9}, {%0,%1,%2,%3};\n"
                        : "+f"(acc[mi][np][1][0]), "+f"(acc[mi][np][1][1]),
                          "+f"(acc[mi][np][1][2]), "+f"(acc[mi][np][1][3])
                        : "r"(af[mi][0]), "r"(af[mi][1]), "r"(af[mi][2]), "r"(af[mi][3]),
                          "r"(bf[np][2]), "r"(bf[np][3]));
                }
        }

        if (kt < 47) {
            *(uint4*)&As[nxt][row][cb]     = ra0;
            *(uint4*)&As[nxt][row][cb + 8] = ra1;
            *(uint4*)&Bs[nxt][row][cb]     = rb0;
            *(uint4*)&Bs[nxt][row][cb + 8] = rb1;
        }
        __syncthreads();
    }

#pragma unroll
    for (int mi = 0; mi < 2; mi++) {
        const long r0 = mbase + warp_m + mi * 16 + gid;
        const long r1 = r0 + 8;
#pragma unroll
        for (int np = 0; np < 4; np++)
#pragma unroll
            for (int s = 0; s < 2; s++) {
                const int c0 = nbase + warp_n + np * 16 + s * 8 + tg * 2;
                if (c0 < N_DIM) {
                    const float bb = bias[c0];
                    g_h[r0 * N_DIM + c0] = acc[mi][np][s][0] + bb;
                    g_h[r1 * N_DIM + c0] = acc[mi][np][s][2] + bb;
                }
                if (c0 + 1 < N_DIM) {
                    const float bb = bias[c0 + 1];
                    g_h[r0 * N_DIM + c0 + 1] = acc[mi][np][s][1] + bb;
                    g_h[r1 * N_DIM + c0 + 1] = acc[mi][np][s][3] + bb;
                }
            }
    }
}

// ---------------------------------------------------------------------------
// Kernel 2: half-size real iFFT.  4 frames per CTA (256 thr, 64 per frame).
//   S[k] = min(exp(h_mag),100) e^{i p}  (bins 0 and 512 realified: identical
//   to Re(ifft) of the raw spectrum).
//   Z[k] = (S[k]+conj(S[512-k])) + i e^{2pi ik/1024}(S[k]-conj(S[512-k]))
//   z = FFT512^{+}(Z), y[2n]=Re z[n]/1024, y[2n+1]=Im z[n]/1024.
//   FFT512 = 3 radix-8 DIT stages on base-8 digit-reversed input.
// ---------------------------------------------------------------------------
#define C45 0.70710678118654752440f

__global__ __launch_bounds__(256) void istft_frame_kernel()
{
    __shared__ float sSr[4][516], sSi[4][516];
    __shared__ float zr[4][512],  zi[4][512];
    __shared__ float t5c[512], t5s[512];

    const int tid = threadIdx.x;
    const int fl  = tid >> 6;        // frame lane 0..3
    const int t   = tid & 63;        // thread within frame
    const int f   = blockIdx.x * 4 + fl;

    t5c[tid]       = g_t5c[tid];
    t5s[tid]       = g_t5s[tid];
    t5c[tid + 256] = g_t5c[tid + 256];
    t5s[tid + 256] = g_t5s[tid + 256];

    const float* hrow = g_h + (long)f * N_DIM;

    // ---- S build (bins 0..512; bins 0,512 imag zeroed) ----
#pragma unroll
    for (int i = 0; i < 8; i++) {
        const int k = t + 64 * i;
        float mag = fminf(__expf(hrow[k]), 100.0f);
        float p = hrow[NBINS + k];
        float s, c;
        __sincosf(p, &s, &c);
        sSr[fl][k] = mag * c;
        sSi[fl][k] = (k == 0) ? 0.0f : mag * s;
    }
    if (t == 0) {
        float mag = fminf(__expf(hrow[512]), 100.0f);
        float p = hrow[NBINS + 512];
        float s, c;
        __sincosf(p, &s, &c);
        sSr[fl][512] = mag * c;
        sSi[fl][512] = 0.0f;
    }
    __syncthreads();

    // ---- Z build, scatter to base-8 digit-reversed positions ----
#pragma unroll
    for (int i = 0; i < 8; i++) {
        const int k = t + 64 * i;
        const float ar = sSr[fl][k],       ai = sSi[fl][k];
        const float br = sSr[fl][512 - k], bi = -sSi[fl][512 - k];
        const float sr = ar + br, si = ai + bi;
        const float dr = ar - br, di = ai - bi;
        const float wc = g_twc[k], ws = g_tws[k];       // e^{+2pi ik/1024}
        const float tr = dr * wc - di * ws;
        const float ti = dr * ws + di * wc;
        const int d = ((k & 7) << 6) | (k & 56) | (k >> 6);
        zr[fl][d] = sr - ti;
        zi[fl][d] = si + tr;
    }
    __syncthreads();

    // ---- 3 radix-8 DIT stages (inverse sign e^{+}) ----
#pragma unroll
    for (int st = 0; st < 3; st++) {
        const int q    = (st == 0) ? 1 : (st == 1) ? 8 : 64;
        const int msc  = (st == 0) ? 64 : (st == 1) ? 8 : 1;  // 512/(8q)
        const int pos  = t & (q - 1);
        const int base = (t / q) * (8 * q) + pos;

        float xr[8], xi[8];
#pragma unroll
        for (int j = 0; j < 8; j++) {
            float vr = zr[fl][base + j * q];
            float vi = zi[fl][base + j * q];
            if (j > 0) {
                const int m = pos * j * msc;
                const float c = t5c[m], s = t5s[m];
                const float nr = vr * c - vi * s;
                vi = vr * s + vi * c;
                vr = nr;
            }
            xr[j] = vr;
            xi[j] = vi;
        }

        // FFT4 of evens (x0,x2,x4,x6) -> E ; odds (x1,x3,x5,x7) -> O
        float E0r, E0i, E1r, E1i, E2r, E2i, E3r, E3i;
        float O0r, O0i, O1r, O1i, O2r, O2i, O3r, O3i;
        {
            const float arr = xr[0] + xr[4], ari = xi[0] + xi[4];
            const float brr = xr[0] - xr[4], bri = xi[0] - xi[4];
            const float crr = xr[2] + xr[6], cri = xi[2] + xi[6];
            const float drr = xr[2] - xr[6], dri = xi[2] - xi[6];
            E0r = arr + crr;  E0i = ari + cri;
            E2r = arr - crr;  E2i = ari - cri;
            E1r = brr - dri;  E1i = bri + drr;      // b + i*d
            E3r = brr + dri;  E3i = bri - drr;      // b - i*d
        }
        {
            const float arr = xr[1] + xr[5], ari = xi[1] + xi[5];
            const float brr = xr[1] - xr[5], bri = xi[1] - xi[5];
            const float crr = xr[3] + xr[7], cri = xi[3] + xi[7];
            const float drr = xr[3] - xr[7], dri = xi[3] - xi[7];
            O0r = arr + crr;  O0i = ari + cri;
            O2r = arr - crr;  O2i = ari - cri;
            O1r = brr - dri;  O1i = bri + drr;
            O3r = brr + dri;  O3i = bri - drr;
        }
        // combine with w8^j = e^{+2pi ij/8}
        const float w1r = C45 * (O1r - O1i), w1i = C45 * (O1r + O1i);
        const float w2r = -O2i,              w2i = O2r;
        const float w3r = -C45 * (O3r + O3i), w3i = C45 * (O3r - O3i);

        zr[fl][base]         = E0r + O0r;  zi[fl][base]         = E0i + O0i;
        zr[fl][base + 4 * q] = E0r - O0r;  zi[fl][base + 4 * q] = E0i - O0i;
        zr[fl][base + 1 * q] = E1r + w1r;  zi[fl][base + 1 * q] = E1i + w1i;
        zr[fl][base + 5 * q] = E1r - w1r;  zi[fl][base + 5 * q] = E1i - w1i;
        zr[fl][base + 2 * q] = E2r + w2r;  zi[fl][base + 2 * q] = E2i + w2i;
        zr[fl][base + 6 * q] = E2r - w2r;  zi[fl][base + 6 * q] = E2i - w2i;
        zr[fl][base + 3 * q] = E3r + w3r;  zi[fl][base + 3 * q] = E3i + w3i;
        zr[fl][base + 7 * q] = E3r - w3r;  zi[fl][base + 7 * q] = E3i - w3i;
        __syncthreads();
    }

    // ---- windowed output: y[2n]=Re z[n], y[2n+1]=Im z[n], * win/1024 ----
    float* frow = g_frames + (long)f * NFFT;
#pragma unroll
    for (int i = 0; i < 8; i++) {
        const int n = t + 64 * i;
        float2 v;
        v.x = zr[fl][n] * (1.0f / 1024.0f) * g_win[2 * n];
        v.y = zi[fl][n] * (1.0f / 1024.0f) * g_win[2 * n + 1];
        *(float2*)(frow + 2 * n) = v;
    }
}

// ---------------------------------------------------------------------------
// Kernel 3: overlap-add + envelope (interior env == 1.5 exactly).
// ---------------------------------------------------------------------------
__global__ __launch_bounds__(256) void ola_kernel(float* __restrict__ out)
{
    const int idx = blockIdx.x * blockDim.x + threadIdx.x;
    if (idx >= NB * OUTL) return;
    const int b = idx / OUTL;
    const int i = idx - b * OUTL;
    const int n = i + PADC;

    const int tmax = min(n >> 8, 2047);
    const int tmin = (n >= NFFT) ? ((n - (NFFT - 1) + (HOP - 1)) >> 8) : 0;

    float sum = 0.0f;
#pragma unroll 4
    for (int t = tmin; t <= tmax; ++t) {
        const int m = n - (t << 8);
        sum += g_frames[(((long)(b * 2048 + t)) << 10) + m];
    }

    float env;
    if (tmax - tmin == 3) {
        env = 1.5f;
    } else {
        env = 0.0f;
        for (int t = tmin; t <= tmax; ++t) {
            const int m = n - (t << 8);
            float w = 0.5f - 0.5f * cosf(6.2831853071795864769f * (float)m * (1.0f / 1024.0f));
            env += w * w;
        }
    }
    out[idx] = sum / env;
}

// ---------------------------------------------------------------------------
extern "C" void kernel_launch(void* const* d_in, const int* in_sizes, int n_in,
                              void* d_out, int out_size)
{
    const float* x    = (const float*)d_in[0];
    const float* W    = (const float*)d_in[1];
    const float* bias = (const float*)d_in[2];
    float* out = (float*)d_out;

    const long na = (long)M_TOT * K_DIM;
    conv_a_kernel<<<(unsigned)((na + 255) / 256), 256>>>(x);
    const long nb = (long)N_PAD * KP;
    conv_b_kernel<<<(unsigned)((nb + 255) / 256), 256>>>(W);
    init_tables_kernel<<<1, 1024>>>();

    dim3 gg(N_PAD / 128, M_TOT / 128);           // (9, 128)
    gemm_mma_kernel<<<gg, 256>>>(bias);

    istft_frame_kernel<<<M_TOT / 4, 256>>>();

    const int total = NB * OUTL;
    ola_kernel<<<(total + 255) / 256, 256>>>(out);
}